// round 8
// baseline (speedup 1.0000x reference)
#include <cuda_runtime.h>

// MultiScaleRoIAlign: 4-level FPN, RoIAlign(aligned=False), OUT=7, SR=2.
// feats: [2,256,200,200],[2,256,100,100],[2,256,50,50],[2,256,25,25] fp32
// boxes: [2,256,4] fp32 -> out: [512,256,7,7] fp32
//
// v8: direct gather (v7 structure) + 2-channel unroll for MLP + guarded
// chunk-1 (no duplicate loads on lanes 17..31). One block (256 thr) per
// RoI; warp = channel pair, lane = bin. Per-lane bin geometry lives in
// registers, constant across the whole channel sweep. No smem, no barriers.

#define NLVL 4

__global__ __launch_bounds__(256) void roi_align_kernel(
    const float* __restrict__ f0, const float* __restrict__ f1,
    const float* __restrict__ f2, const float* __restrict__ f3,
    const float* __restrict__ boxes, float* __restrict__ out)
{
    const int r    = blockIdx.x;     // roi 0..511
    const int tid  = threadIdx.x;
    const int w    = tid >> 5;       // warp 0..7
    const int lane = tid & 31;
    const int b    = r >> 8;

    // ---- per-RoI geometry ----
    const float bx1 = boxes[r * 4 + 0];
    const float by1 = boxes[r * 4 + 1];
    const float bx2 = boxes[r * 4 + 2];
    const float by2 = boxes[r * 4 + 3];

    const float area = (bx2 - bx1) * (by2 - by1);
    float lv = floorf(4.0f + log2f(sqrtf(area) / 224.0f + 1e-6f));
    lv = fminf(fmaxf(lv, 2.0f), 5.0f);
    const int level = (int)lv - 2;

    const int   Htab[NLVL]  = {200, 100, 50, 25};
    const float sctab[NLVL] = {0.25f, 0.125f, 0.0625f, 0.03125f};
    const int   H  = Htab[level];
    const int   W  = H;
    const float sc = sctab[level];
    const float* feat = (level == 0) ? f0 : (level == 1) ? f1 : (level == 2) ? f2 : f3;

    const float x1 = bx1 * sc, y1 = by1 * sc;
    const float roi_w = fmaxf(bx2 * sc - x1, 1.0f);
    const float roi_h = fmaxf(by2 * sc - y1, 1.0f);
    const float bin_w = roi_w / 7.0f;
    const float bin_h = roi_h / 7.0f;

    // ---- per-lane bin geometry, fully in registers ----
    int   Ry[2][4], Xc[2][4];
    float Cy[2][4], Cx[2][4];

    #pragma unroll
    for (int chk = 0; chk < 2; chk++) {
        int bin = lane + 32 * chk;
        if (bin > 48) bin = 0;                 // lanes >=17 chunk1: dummy (guarded later)
        const int ph = bin / 7;
        const int pw = bin - 7 * ph;

        #pragma unroll
        for (int s = 0; s < 2; s++) {
            // y tap
            {
                const float g   = (float)ph + ((float)s + 0.5f) * 0.5f;
                float pos = y1 + g * bin_h;
                const float vld = (pos >= -1.0f && pos <= (float)H) ? 0.25f : 0.0f; // fold /4
                pos = fmaxf(pos, 0.0f);
                int lo = (int)pos, hi;
                if (lo >= H - 1) { lo = H - 1; hi = H - 1; pos = (float)lo; }
                else             { hi = lo + 1; }
                const float fr = pos - (float)lo;
                Ry[chk][2 * s + 0] = lo * W;
                Ry[chk][2 * s + 1] = hi * W;
                Cy[chk][2 * s + 0] = vld * (1.0f - fr);
                Cy[chk][2 * s + 1] = vld * fr;
            }
            // x tap
            {
                const float g   = (float)pw + ((float)s + 0.5f) * 0.5f;
                float pos = x1 + g * bin_w;
                const float vld = (pos >= -1.0f && pos <= (float)W) ? 1.0f : 0.0f;
                pos = fmaxf(pos, 0.0f);
                int lo = (int)pos, hi;
                if (lo >= W - 1) { lo = W - 1; hi = W - 1; pos = (float)lo; }
                else             { hi = lo + 1; }
                const float fr = pos - (float)lo;
                Xc[chk][2 * s + 0] = lo;
                Xc[chk][2 * s + 1] = hi;
                Cx[chk][2 * s + 0] = vld * (1.0f - fr);
                Cx[chk][2 * s + 1] = vld * fr;
            }
        }
    }

    const bool hi_lane = (lane < 17);

    // ---- sweep 32 channels per warp, unrolled x2 for MLP ----
    const size_t plane = (size_t)H * W;
    const float* fp = feat + ((size_t)b * 256 + (size_t)w * 32) * plane;
    float* op = out + ((size_t)r * 256 + (size_t)w * 32) * 49;

    #pragma unroll 1
    for (int k = 0; k < 32; k += 2) {
        const float* fpa = fp;
        const float* fpb = fp + plane;

        float a0 = 0.0f, a1 = 0.0f, b0 = 0.0f, b1 = 0.0f;

        // chunk 0 for both channels (independent load streams)
        #pragma unroll
        for (int i = 0; i < 4; i++) {
            const float* A = fpa + Ry[0][i];
            const float* B = fpb + Ry[0][i];
            a0 += Cy[0][i] * (Cx[0][0] * A[Xc[0][0]] + Cx[0][1] * A[Xc[0][1]]
                            + Cx[0][2] * A[Xc[0][2]] + Cx[0][3] * A[Xc[0][3]]);
            b0 += Cy[0][i] * (Cx[0][0] * B[Xc[0][0]] + Cx[0][1] * B[Xc[0][1]]
                            + Cx[0][2] * B[Xc[0][2]] + Cx[0][3] * B[Xc[0][3]]);
        }
        // chunk 1 for both channels, only on live lanes (no wasted loads)
        if (hi_lane) {
            #pragma unroll
            for (int i = 0; i < 4; i++) {
                const float* A = fpa + Ry[1][i];
                const float* B = fpb + Ry[1][i];
                a1 += Cy[1][i] * (Cx[1][0] * A[Xc[1][0]] + Cx[1][1] * A[Xc[1][1]]
                                + Cx[1][2] * A[Xc[1][2]] + Cx[1][3] * A[Xc[1][3]]);
                b1 += Cy[1][i] * (Cx[1][0] * B[Xc[1][0]] + Cx[1][1] * B[Xc[1][1]]
                                + Cx[1][2] * B[Xc[1][2]] + Cx[1][3] * B[Xc[1][3]]);
            }
        }

        op[lane] = a0;
        op[49 + lane] = b0;
        if (hi_lane) {
            op[32 + lane] = a1;
            op[49 + 32 + lane] = b1;
        }

        fp += 2 * plane;
        op += 2 * 49;
    }
}

extern "C" void kernel_launch(void* const* d_in, const int* in_sizes, int n_in,
                              void* d_out, int out_size) {
    const int nroi = in_sizes[4] / 4;   // 512
    roi_align_kernel<<<nroi, 256>>>(
        (const float*)d_in[0], (const float*)d_in[1],
        (const float*)d_in[2], (const float*)d_in[3],
        (const float*)d_in[4], (float*)d_out);
}